// round 12
// baseline (speedup 1.0000x reference)
#include <cuda_runtime.h>
#include <cuda_fp16.h>

// ---------------------------------------------------------------------------
// GIN encoder. Bucketed-CSR pipeline + algebraic BN fold, 8 launches:
//   memset -> fill -> cvt(x->fp16) -> agg0 -> mlp0 -> agg1(+ow0 tail)
//   -> mlp1 -> ow1
// Activations stored fp16 (gather bandwidth halved); all math fp32.
//   out[g] = scale * poolsum_preBN[g] + cnt[g] * shift
//   hin1   = sc0*(h0[n] + sum h0[src]) + (1+deg)*sh0     (x0 never stored)
// ---------------------------------------------------------------------------

#define MAX_N 100000
#define MAX_G 1024
#define DIM 64
#define BN_EPS 1e-5f
#define SLOTS 64

// per-layer reduction buffer: pool[MAX_G*DIM] | sumsq[DIM] | totsum[DIM]
#define PS_FLOATS (MAX_G * DIM + 2 * DIM)

// single zeroed scratch region: ps0 | ps1 | deg[MAX_N] | cnt[MAX_G]
__device__ __align__(16) unsigned int g_zeroed[2 * PS_FLOATS + MAX_N + MAX_G];
#define DEGP ((int*)g_zeroed + 2 * PS_FLOATS)
#define CNTP (DEGP + MAX_N)

__device__ __align__(16) __half g_xh [MAX_N * DIM];  // fp16 copy of x
__device__ __align__(16) __half g_h0h[MAX_N * DIM];  // layer-0 pre-BN h, fp16
__device__ __align__(16) __half g_hin[MAX_N * DIM];  // MLP inputs, fp16
__device__ __align__(16) int g_srcidx[MAX_N * SLOTS];

// dynamic smem for mlp_kernel (256 nodes/block):
// Ws[4096] | rows[256*65] | bats[256]
#define MLP_NODES 256
#define MLP_SMEM_WORDS (4096 + MLP_NODES * 65 + MLP_NODES)
#define MLP_SMEM_BYTES (MLP_SMEM_WORDS * 4)

// ---------------- helpers --------------------------------------------------
static __device__ __forceinline__ unsigned long long ffma2(
    unsigned long long a, unsigned long long b, unsigned long long c) {
    unsigned long long d;
    asm("fma.rn.f32x2 %0, %1, %2, %3;" : "=l"(d) : "l"(a), "l"(b), "l"(c));
    return d;
}
static __device__ __forceinline__ unsigned long long pack2(float x, float y) {
    unsigned long long r;
    asm("mov.b64 %0, {%1, %2};" : "=l"(r) : "f"(x), "f"(y));
    return r;
}
static __device__ __forceinline__ float2 unpack2(unsigned long long v) {
    float2 f;
    asm("mov.b64 {%0, %1}, %2;" : "=f"(f.x), "=f"(f.y) : "l"(v));
    return f;
}
static __device__ __forceinline__ float tanha(float x) {
    float y;
    asm("tanh.approx.f32 %0, %1;" : "=f"(y) : "f"(x));
    return y;
}
static __device__ __forceinline__ float4 h4_to_f4(uint2 v) {
    __half2 a = *reinterpret_cast<__half2*>(&v.x);
    __half2 b = *reinterpret_cast<__half2*>(&v.y);
    float2 fa = __half22float2(a);
    float2 fb = __half22float2(b);
    return make_float4(fa.x, fa.y, fb.x, fb.y);
}
static __device__ __forceinline__ uint2 f4_to_h4(float4 f) {
    __half2 a = __float22half2_rn(make_float2(f.x, f.y));
    __half2 b = __float22half2_rn(make_float2(f.z, f.w));
    uint2 v;
    v.x = *reinterpret_cast<unsigned int*>(&a);
    v.y = *reinterpret_cast<unsigned int*>(&b);
    return v;
}

// ---------------- bucket fill + graph counts -------------------------------
__global__ void fill_cnt_kernel(const int* __restrict__ ei,
                                const int* __restrict__ batch, int E, int N) {
    int t = blockIdx.x * blockDim.x + threadIdx.x;
    if (t < E) {
        int s = __ldg(ei + t);
        int d = __ldg(ei + E + t);
        int pos = atomicAdd(&DEGP[d], 1);
        if (pos < SLOTS) g_srcidx[d * SLOTS + pos] = s;
    }
    if (t < N) atomicAdd(&CNTP[__ldg(batch + t)], 1);
}

// ---------------- x -> fp16 conversion -------------------------------------
__global__ void cvt_kernel(const float* __restrict__ x, int CV) {
    int t = blockIdx.x * blockDim.x + threadIdx.x;
    if (t < CV) {
        float4 v = __ldg(&reinterpret_cast<const float4*>(x)[t]);
        reinterpret_cast<uint2*>(g_xh)[t] = f4_to_h4(v);
    }
}

// ---------------- aggregation (fp16 gather, fp32 accumulate) ---------------
// 16 lanes per node (uint2 = 4 halves per lane), 8 nodes per 128-thread block.
// AFFINE: folds previous layer's BN inline; tail blocks do outwrite0.
template <bool AFFINE>
__global__ __launch_bounds__(128) void aggregate_kernel(
    const __half* __restrict__ xh, __half* __restrict__ hout,
    const float* __restrict__ psPrev,
    const float* __restrict__ gamma, const float* __restrict__ beta,
    float* __restrict__ out, float invN, int N, int G, int aggBlocks) {
    if (AFFINE && (int)blockIdx.x >= aggBlocks) {
        // outwrite duty for the PREVIOUS layer (col_off = 0)
        int idx = ((int)blockIdx.x - aggBlocks) * 128 + threadIdx.x;
        if (idx < G * DIM) {
            int g = idx >> 6, j = idx & 63;
            float mean = __ldg(psPrev + MAX_G * DIM + DIM + j) * invN;
            float var  = __ldg(psPrev + MAX_G * DIM + j) * invN - mean * mean;
            float sc   = __ldg(gamma + j) * rsqrtf(var + BN_EPS);
            float sh   = __ldg(beta + j) - mean * sc;
            out[g * 128 + j] =
                sc * psPrev[idx] + (float)__ldg(&CNTP[g]) * sh;
        }
        return;
    }
    int node = blockIdx.x * 8 + (threadIdx.x >> 4);
    int c = threadIdx.x & 15;
    if (node >= N) return;
    int deg = __ldg(&DEGP[node]);
    const uint2* x2 = reinterpret_cast<const uint2*>(xh);
    const int4* idx4 = reinterpret_cast<const int4*>(g_srcidx + node * SLOTS);
    float4 acc = h4_to_f4(__ldg(&x2[node * 16 + c]));
    int e = 0;
    for (; e + 4 <= deg; e += 4) {
        int4 s = __ldg(&idx4[e >> 2]);
        float4 v0 = h4_to_f4(__ldg(&x2[s.x * 16 + c]));
        float4 v1 = h4_to_f4(__ldg(&x2[s.y * 16 + c]));
        float4 v2 = h4_to_f4(__ldg(&x2[s.z * 16 + c]));
        float4 v3 = h4_to_f4(__ldg(&x2[s.w * 16 + c]));
        acc.x += (v0.x + v1.x) + (v2.x + v3.x);
        acc.y += (v0.y + v1.y) + (v2.y + v3.y);
        acc.z += (v0.z + v1.z) + (v2.z + v3.z);
        acc.w += (v0.w + v1.w) + (v2.w + v3.w);
    }
    for (; e < deg; e++) {
        int s = __ldg(g_srcidx + node * SLOTS + e);
        float4 v0 = h4_to_f4(__ldg(&x2[s * 16 + c]));
        acc.x += v0.x;
        acc.y += v0.y;
        acc.z += v0.z;
        acc.w += v0.w;
    }
    if (AFFINE) {
        const float4* ss4 = reinterpret_cast<const float4*>(psPrev + MAX_G * DIM);
        const float4* ts4 = reinterpret_cast<const float4*>(psPrev + MAX_G * DIM + DIM);
        float4 ssq = __ldg(&ss4[c]);
        float4 tot = __ldg(&ts4[c]);
        float4 gm = __ldg(&reinterpret_cast<const float4*>(gamma)[c]);
        float4 bt = __ldg(&reinterpret_cast<const float4*>(beta)[c]);
        float f = (float)(1 + deg);
        float mx = tot.x * invN, my = tot.y * invN,
              mz = tot.z * invN, mw = tot.w * invN;
        float scx = gm.x * rsqrtf(ssq.x * invN - mx * mx + BN_EPS);
        float scy = gm.y * rsqrtf(ssq.y * invN - my * my + BN_EPS);
        float scz = gm.z * rsqrtf(ssq.z * invN - mz * mz + BN_EPS);
        float scw = gm.w * rsqrtf(ssq.w * invN - mw * mw + BN_EPS);
        acc.x = acc.x * scx + f * (bt.x - mx * scx);
        acc.y = acc.y * scy + f * (bt.y - my * scy);
        acc.z = acc.z * scz + f * (bt.z - mz * scz);
        acc.w = acc.w * scw + f * (bt.w - mw * scw);
    }
    reinterpret_cast<uint2*>(hout)[node * 16 + c] = f4_to_h4(acc);
}

// ---------------- MLP stage (shared weights, f32x2 FMA, MUFU tanh) ---------
static __device__ __forceinline__ void mlp_stage(float* row,
                                                 const float* Ws,
                                                 const float* __restrict__ bias) {
    unsigned long long acc[32];
    const ulonglong2* bp = reinterpret_cast<const ulonglong2*>(bias);
#pragma unroll
    for (int j = 0; j < 16; j++) {
        ulonglong2 b = __ldg(&bp[j]);
        acc[2 * j + 0] = b.x;
        acc[2 * j + 1] = b.y;
    }

#pragma unroll 4
    for (int k = 0; k < DIM; k++) {
        float xk = row[k];
        unsigned long long xx = pack2(xk, xk);
        const ulonglong2* Wp =
            reinterpret_cast<const ulonglong2*>(Ws + (k << 6));
#pragma unroll
        for (int j = 0; j < 16; j++) {
            ulonglong2 w = Wp[j];
            acc[2 * j + 0] = ffma2(xx, w.x, acc[2 * j + 0]);
            acc[2 * j + 1] = ffma2(xx, w.y, acc[2 * j + 1]);
        }
    }
#pragma unroll
    for (int j = 0; j < 32; j++) {
        float2 v = unpack2(acc[j]);
        row[2 * j + 0] = tanha(v.x);
        row[2 * j + 1] = tanha(v.y);
    }
}

// ---------------- MLP + BN stats + pre-BN pool sums ------------------------
// 256 nodes per 256-thread block; staged weight buffer in dynamic smem
// (84KB -> 2 blocks/SM, 512 threads/SM). Phase-3 reduction is 4-way split.
template <bool WRITE_H>
__global__ __launch_bounds__(MLP_NODES) void mlp_kernel(
    const __half* __restrict__ hin,
    const float* __restrict__ W1, const float* __restrict__ b1,
    const float* __restrict__ W2, const float* __restrict__ b2,
    const int* __restrict__ batch, __half* __restrict__ hout,
    float* __restrict__ ps, int N) {
    extern __shared__ float sm[];
    float* Ws   = sm;                            // 4096
    float* rows = sm + 4096;                     // 256 * 65
    int*   bats = (int*)(sm + 4096 + MLP_NODES * 65);  // 256

    float* pool   = ps;
    float* stats  = ps + MAX_G * DIM;
    float* totsum = ps + MAX_G * DIM + DIM;

    int tid  = threadIdx.x;
    int base = blockIdx.x * MLP_NODES;
    int node = base + tid;

    for (int i = tid; i < 4096; i += MLP_NODES) Ws[i] = __ldg(W1 + i);
    bats[tid] = __ldg(batch + (node < N ? node : N - 1));

    float* myrow = rows + tid * 65;
    if (node < N) {
        const uint2* h2 = reinterpret_cast<const uint2*>(hin);
#pragma unroll
        for (int c = 0; c < 16; c++) {
            float4 v = h4_to_f4(__ldg(&h2[node * 16 + c]));
            myrow[4 * c + 0] = v.x;
            myrow[4 * c + 1] = v.y;
            myrow[4 * c + 2] = v.z;
            myrow[4 * c + 3] = v.w;
        }
    } else {
#pragma unroll
        for (int c = 0; c < DIM; c++) myrow[c] = 0.0f;
    }
    __syncthreads();                       // W1 + rows ready

    if (node < N) mlp_stage(myrow, Ws, b1);
    __syncthreads();                       // all done reading W1

    for (int i = tid; i < 4096; i += MLP_NODES) Ws[i] = __ldg(W2 + i);
    __syncthreads();                       // W2 ready

    if (node < N) mlp_stage(myrow, Ws, b2);
    __syncthreads();                       // rows final for phase 3

    if (WRITE_H) {
        __half2* ho = reinterpret_cast<__half2*>(hout);
        for (int i = tid; i < MLP_NODES * 32; i += MLP_NODES) {
            int r = i >> 5, c = (i & 31) << 1;
            if (base + r < N) {
                ho[(base + r) * 32 + (i & 31)] = __float22half2_rn(
                    make_float2(rows[r * 65 + c], rows[r * 65 + c + 1]));
            }
        }
    }

    // 4-way phase 3 (padded rows are zero):
    //   duty 0: segmented pre-BN pool sums + total;  duty 1: sum of squares
    //   half 0: rows [0,128);                        half 1: rows [128,256)
    {
        int j    = tid & 63;
        int duty = (tid >> 6) & 1;
        int half = (tid >> 7) & 1;
        int r0 = half << 7, r1 = r0 + 128;
        if (duty == 0) {
            int cur = bats[r0];
            float acc = 0.0f;
            float tot = 0.0f;
            for (int r = r0; r < r1; r++) {
                int g = bats[r];
                float v = rows[r * 65 + j];
                if (g != cur) {
                    atomicAdd(&pool[cur * DIM + j], acc);
                    acc = 0.0f;
                    cur = g;
                }
                acc += v;
                tot += v;
            }
            atomicAdd(&pool[cur * DIM + j], acc);
            atomicAdd(&totsum[j], tot);
        } else {
            float s = 0.0f;
            for (int r = r0; r < r1; r++) {
                float v = rows[r * 65 + j];
                s += v * v;
            }
            atomicAdd(&stats[j], s);
        }
    }
}

// ---------------- output write (BN folded, scale/shift inline) -------------
__global__ void outwrite_kernel(const float* __restrict__ ps,
                                const float* __restrict__ gamma,
                                const float* __restrict__ beta,
                                float* __restrict__ out, int col_off,
                                float invN, int G) {
    int idx = blockIdx.x * blockDim.x + threadIdx.x;
    if (idx >= G * DIM) return;
    int g = idx >> 6, j = idx & 63;
    float mean = __ldg(ps + MAX_G * DIM + DIM + j) * invN;
    float var  = __ldg(ps + MAX_G * DIM + j) * invN - mean * mean;
    float sc   = __ldg(gamma + j) * rsqrtf(var + BN_EPS);
    float sh   = __ldg(beta + j) - mean * sc;
    out[g * 128 + col_off + j] = sc * ps[idx] + (float)__ldg(&CNTP[g]) * sh;
}

// ---------------------------------------------------------------------------
extern "C" void kernel_launch(void* const* d_in, const int* in_sizes, int n_in,
                              void* d_out, int out_size) {
    const float* x       = (const float*)d_in[0];
    const float* W1_0    = (const float*)d_in[1];
    const float* b1_0    = (const float*)d_in[2];
    const float* W2_0    = (const float*)d_in[3];
    const float* b2_0    = (const float*)d_in[4];
    const float* gamma_0 = (const float*)d_in[5];
    const float* beta_0  = (const float*)d_in[6];
    const float* W1_1    = (const float*)d_in[7];
    const float* b1_1    = (const float*)d_in[8];
    const float* W2_1    = (const float*)d_in[9];
    const float* b2_1    = (const float*)d_in[10];
    const float* gamma_1 = (const float*)d_in[11];
    const float* beta_1  = (const float*)d_in[12];
    const int*   ei      = (const int*)d_in[13];
    const int*   batch   = (const int*)d_in[14];

    int N = in_sizes[0] / DIM;
    int E = in_sizes[13] / 2;
    int G = out_size / 128;
    float* out = (float*)d_out;

    void *zero_p, *xh_p, *h0_p, *hin_p;
    cudaGetSymbolAddress(&zero_p, g_zeroed);
    cudaGetSymbolAddress(&xh_p, g_xh);
    cudaGetSymbolAddress(&h0_p, g_h0h);
    cudaGetSymbolAddress(&hin_p, g_hin);

    float* ps0 = (float*)zero_p;
    float* ps1 = ps0 + PS_FLOATS;

    cudaFuncSetAttribute(mlp_kernel<true>,
                         cudaFuncAttributeMaxDynamicSharedMemorySize,
                         MLP_SMEM_BYTES);
    cudaFuncSetAttribute(mlp_kernel<false>,
                         cudaFuncAttributeMaxDynamicSharedMemorySize,
                         MLP_SMEM_BYTES);

    int CV = N * DIM / 4;   // float4 conversion threads
    int work = (E > N) ? E : N;
    int fill_blocks = (work + 255) / 256;
    int cvt_blocks  = (CV + 255) / 256;
    int agg_blocks  = (N + 7) / 8;
    int ow_tail     = (G * DIM + 127) / 128;
    int mlp_blocks  = (N + MLP_NODES - 1) / MLP_NODES;
    int ow_blocks   = (G * DIM + 255) / 256;
    float invN = 1.0f / (float)N;

    // ---- one memset for all zeroed scratch ----
    cudaMemsetAsync(zero_p, 0, sizeof(g_zeroed));
    fill_cnt_kernel<<<fill_blocks, 256>>>(ei, batch, E, N);
    cvt_kernel<<<cvt_blocks, 256>>>(x, CV);

    // ---------------- layer 0 ----------------
    aggregate_kernel<false><<<agg_blocks, 128>>>(
        (const __half*)xh_p, (__half*)hin_p, nullptr, nullptr, nullptr,
        nullptr, invN, N, G, agg_blocks);
    mlp_kernel<true><<<mlp_blocks, MLP_NODES, MLP_SMEM_BYTES>>>(
        (const __half*)hin_p, W1_0, b1_0, W2_0, b2_0, batch,
        (__half*)h0_p, ps0, N);

    // ---------------- layer 1 (agg folds BN0 inline; tail = outwrite0) -----
    aggregate_kernel<true><<<agg_blocks + ow_tail, 128>>>(
        (const __half*)h0_p, (__half*)hin_p, ps0, gamma_0, beta_0, out,
        invN, N, G, agg_blocks);
    mlp_kernel<false><<<mlp_blocks, MLP_NODES, MLP_SMEM_BYTES>>>(
        (const __half*)hin_p, W1_1, b1_1, W2_1, b2_1, batch,
        nullptr, ps1, N);
    outwrite_kernel<<<ow_blocks, 256>>>(ps1, gamma_1, beta_1, out, 64, invN, G);
}

// round 14
// speedup vs baseline: 1.0496x; 1.0496x over previous
#include <cuda_runtime.h>
#include <cuda_fp16.h>

// ---------------------------------------------------------------------------
// GIN encoder. Bucketed-CSR pipeline + algebraic BN fold, 8 launches:
//   memset -> fill -> cvt(x->fp16) -> agg0 -> mlp0 -> agg1(+ow0 tail)
//   -> mlp1 -> ow1
// Activations stored fp16 (gather bandwidth halved); all math fp32.
// MLP: 128 nodes / 256 threads per block, 2 threads per node (32 outputs
// each), both weight matrices resident in smem (66.5KB -> 3 blocks/SM).
//   out[g] = scale * poolsum_preBN[g] + cnt[g] * shift
//   hin1   = sc0*(h0[n] + sum h0[src]) + (1+deg)*sh0     (x0 never stored)
// ---------------------------------------------------------------------------

#define MAX_N 100000
#define MAX_G 1024
#define DIM 64
#define BN_EPS 1e-5f
#define SLOTS 64

// per-layer reduction buffer: pool[MAX_G*DIM] | sumsq[DIM] | totsum[DIM]
#define PS_FLOATS (MAX_G * DIM + 2 * DIM)

// single zeroed scratch region: ps0 | ps1 | deg[MAX_N] | cnt[MAX_G]
__device__ __align__(16) unsigned int g_zeroed[2 * PS_FLOATS + MAX_N + MAX_G];
#define DEGP ((int*)g_zeroed + 2 * PS_FLOATS)
#define CNTP (DEGP + MAX_N)

__device__ __align__(16) __half g_xh [MAX_N * DIM];  // fp16 copy of x
__device__ __align__(16) __half g_h0h[MAX_N * DIM];  // layer-0 pre-BN h, fp16
__device__ __align__(16) __half g_hin[MAX_N * DIM];  // MLP inputs, fp16
__device__ __align__(16) int g_srcidx[MAX_N * SLOTS];

// dynamic smem for mlp_kernel: W1|W2 [8192] | rows[128*65] | bats[128]
#define MLP_SMEM_WORDS (8192 + 128 * 65 + 128)
#define MLP_SMEM_BYTES (MLP_SMEM_WORDS * 4)

// ---------------- helpers --------------------------------------------------
static __device__ __forceinline__ unsigned long long ffma2(
    unsigned long long a, unsigned long long b, unsigned long long c) {
    unsigned long long d;
    asm("fma.rn.f32x2 %0, %1, %2, %3;" : "=l"(d) : "l"(a), "l"(b), "l"(c));
    return d;
}
static __device__ __forceinline__ unsigned long long pack2(float x, float y) {
    unsigned long long r;
    asm("mov.b64 %0, {%1, %2};" : "=l"(r) : "f"(x), "f"(y));
    return r;
}
static __device__ __forceinline__ float2 unpack2(unsigned long long v) {
    float2 f;
    asm("mov.b64 {%0, %1}, %2;" : "=f"(f.x), "=f"(f.y) : "l"(v));
    return f;
}
static __device__ __forceinline__ float tanha(float x) {
    float y;
    asm("tanh.approx.f32 %0, %1;" : "=f"(y) : "f"(x));
    return y;
}
static __device__ __forceinline__ float4 h4_to_f4(uint2 v) {
    __half2 a = *reinterpret_cast<__half2*>(&v.x);
    __half2 b = *reinterpret_cast<__half2*>(&v.y);
    float2 fa = __half22float2(a);
    float2 fb = __half22float2(b);
    return make_float4(fa.x, fa.y, fb.x, fb.y);
}
static __device__ __forceinline__ uint2 f4_to_h4(float4 f) {
    __half2 a = __float22half2_rn(make_float2(f.x, f.y));
    __half2 b = __float22half2_rn(make_float2(f.z, f.w));
    uint2 v;
    v.x = *reinterpret_cast<unsigned int*>(&a);
    v.y = *reinterpret_cast<unsigned int*>(&b);
    return v;
}

// ---------------- bucket fill + graph counts -------------------------------
__global__ void fill_cnt_kernel(const int* __restrict__ ei,
                                const int* __restrict__ batch, int E, int N) {
    int t = blockIdx.x * blockDim.x + threadIdx.x;
    if (t < E) {
        int s = __ldg(ei + t);
        int d = __ldg(ei + E + t);
        int pos = atomicAdd(&DEGP[d], 1);
        if (pos < SLOTS) g_srcidx[d * SLOTS + pos] = s;
    }
    if (t < N) atomicAdd(&CNTP[__ldg(batch + t)], 1);
}

// ---------------- x -> fp16 conversion -------------------------------------
__global__ void cvt_kernel(const float* __restrict__ x, int CV) {
    int t = blockIdx.x * blockDim.x + threadIdx.x;
    if (t < CV) {
        float4 v = __ldg(&reinterpret_cast<const float4*>(x)[t]);
        reinterpret_cast<uint2*>(g_xh)[t] = f4_to_h4(v);
    }
}

// ---------------- aggregation (fp16 gather, fp32 accumulate) ---------------
// 16 lanes per node (uint2 = 4 halves per lane), 8 nodes per 128-thread block.
// AFFINE: folds previous layer's BN inline; tail blocks do outwrite0.
template <bool AFFINE>
__global__ __launch_bounds__(128) void aggregate_kernel(
    const __half* __restrict__ xh, __half* __restrict__ hout,
    const float* __restrict__ psPrev,
    const float* __restrict__ gamma, const float* __restrict__ beta,
    float* __restrict__ out, float invN, int N, int G, int aggBlocks) {
    if (AFFINE && (int)blockIdx.x >= aggBlocks) {
        // outwrite duty for the PREVIOUS layer (col_off = 0)
        int idx = ((int)blockIdx.x - aggBlocks) * 128 + threadIdx.x;
        if (idx < G * DIM) {
            int g = idx >> 6, j = idx & 63;
            float mean = __ldg(psPrev + MAX_G * DIM + DIM + j) * invN;
            float var  = __ldg(psPrev + MAX_G * DIM + j) * invN - mean * mean;
            float sc   = __ldg(gamma + j) * rsqrtf(var + BN_EPS);
            float sh   = __ldg(beta + j) - mean * sc;
            out[g * 128 + j] =
                sc * psPrev[idx] + (float)__ldg(&CNTP[g]) * sh;
        }
        return;
    }
    int node = blockIdx.x * 8 + (threadIdx.x >> 4);
    int c = threadIdx.x & 15;
    if (node >= N) return;
    int deg = __ldg(&DEGP[node]);
    const uint2* x2 = reinterpret_cast<const uint2*>(xh);
    const int4* idx4 = reinterpret_cast<const int4*>(g_srcidx + node * SLOTS);
    float4 acc = h4_to_f4(__ldg(&x2[node * 16 + c]));
    int e = 0;
    for (; e + 4 <= deg; e += 4) {
        int4 s = __ldg(&idx4[e >> 2]);
        float4 v0 = h4_to_f4(__ldg(&x2[s.x * 16 + c]));
        float4 v1 = h4_to_f4(__ldg(&x2[s.y * 16 + c]));
        float4 v2 = h4_to_f4(__ldg(&x2[s.z * 16 + c]));
        float4 v3 = h4_to_f4(__ldg(&x2[s.w * 16 + c]));
        acc.x += (v0.x + v1.x) + (v2.x + v3.x);
        acc.y += (v0.y + v1.y) + (v2.y + v3.y);
        acc.z += (v0.z + v1.z) + (v2.z + v3.z);
        acc.w += (v0.w + v1.w) + (v2.w + v3.w);
    }
    for (; e < deg; e++) {
        int s = __ldg(g_srcidx + node * SLOTS + e);
        float4 v0 = h4_to_f4(__ldg(&x2[s * 16 + c]));
        acc.x += v0.x;
        acc.y += v0.y;
        acc.z += v0.z;
        acc.w += v0.w;
    }
    if (AFFINE) {
        const float4* ss4 = reinterpret_cast<const float4*>(psPrev + MAX_G * DIM);
        const float4* ts4 = reinterpret_cast<const float4*>(psPrev + MAX_G * DIM + DIM);
        float4 ssq = __ldg(&ss4[c]);
        float4 tot = __ldg(&ts4[c]);
        float4 gm = __ldg(&reinterpret_cast<const float4*>(gamma)[c]);
        float4 bt = __ldg(&reinterpret_cast<const float4*>(beta)[c]);
        float f = (float)(1 + deg);
        float mx = tot.x * invN, my = tot.y * invN,
              mz = tot.z * invN, mw = tot.w * invN;
        float scx = gm.x * rsqrtf(ssq.x * invN - mx * mx + BN_EPS);
        float scy = gm.y * rsqrtf(ssq.y * invN - my * my + BN_EPS);
        float scz = gm.z * rsqrtf(ssq.z * invN - mz * mz + BN_EPS);
        float scw = gm.w * rsqrtf(ssq.w * invN - mw * mw + BN_EPS);
        acc.x = acc.x * scx + f * (bt.x - mx * scx);
        acc.y = acc.y * scy + f * (bt.y - my * scy);
        acc.z = acc.z * scz + f * (bt.z - mz * scz);
        acc.w = acc.w * scw + f * (bt.w - mw * scw);
    }
    reinterpret_cast<uint2*>(hout)[node * 16 + c] = f4_to_h4(acc);
}

// ---------------- MLP half-stage (32 outputs per thread) -------------------
// Computes acc = bias + row @ W[:, half*32 : half*32+32]. No writeback here
// (caller barriers, then tanh+writeback) so partner thread can finish reads.
static __device__ __forceinline__ void mlp_half_acc(
    const float* row, const float* Wbase, int halfOfs,
    const float* __restrict__ bias, unsigned long long* acc) {
    const ulonglong2* bp =
        reinterpret_cast<const ulonglong2*>(bias + halfOfs);
#pragma unroll
    for (int j = 0; j < 8; j++) {
        ulonglong2 b = __ldg(&bp[j]);
        acc[2 * j + 0] = b.x;
        acc[2 * j + 1] = b.y;
    }
#pragma unroll 4
    for (int k = 0; k < DIM; k++) {
        float xk = row[k];
        unsigned long long xx = pack2(xk, xk);
        const ulonglong2* Wp =
            reinterpret_cast<const ulonglong2*>(Wbase + (k << 6) + halfOfs);
#pragma unroll
        for (int j = 0; j < 8; j++) {
            ulonglong2 w = Wp[j];
            acc[2 * j + 0] = ffma2(xx, w.x, acc[2 * j + 0]);
            acc[2 * j + 1] = ffma2(xx, w.y, acc[2 * j + 1]);
        }
    }
}
static __device__ __forceinline__ void mlp_half_store(
    float* row, int halfOfs, const unsigned long long* acc) {
#pragma unroll
    for (int j = 0; j < 16; j++) {
        float2 v = unpack2(acc[j]);
        row[halfOfs + 2 * j + 0] = tanha(v.x);
        row[halfOfs + 2 * j + 1] = tanha(v.y);
    }
}

// ---------------- MLP + BN stats + pre-BN pool sums ------------------------
// 128 nodes / 256 threads per block; 2 threads per node (output halves).
// W1|W2 both resident in smem (no staging). 66.5KB -> 3 blocks/SM.
template <bool WRITE_H>
__global__ __launch_bounds__(256) void mlp_kernel(
    const __half* __restrict__ hin,
    const float* __restrict__ W1, const float* __restrict__ b1,
    const float* __restrict__ W2, const float* __restrict__ b2,
    const int* __restrict__ batch, __half* __restrict__ hout,
    float* __restrict__ ps, int N) {
    extern __shared__ float sm[];
    float* Ws   = sm;                            // 8192: W1 | W2
    float* rows = sm + 8192;                     // 128 * 65
    int*   bats = (int*)(sm + 8192 + 128 * 65);  // 128

    float* pool   = ps;
    float* stats  = ps + MAX_G * DIM;
    float* totsum = ps + MAX_G * DIM + DIM;

    int tid  = threadIdx.x;
    int base = blockIdx.x * 128;

    for (int i = tid; i < 4096; i += 256) {
        Ws[i]        = __ldg(W1 + i);
        Ws[4096 + i] = __ldg(W2 + i);
    }
    if (tid < 128) {
        int n = base + tid;
        bats[tid] = __ldg(batch + (n < N ? n : N - 1));
    }

    // stage rows: 2 threads per node, 8 uint2 (32 halves) each
    {
        int nl = tid >> 1;
        int c0 = (tid & 1) * 8;
        int node = base + nl;
        float* r = rows + nl * 65 + c0 * 4;
        if (node < N) {
            const uint2* h2 = reinterpret_cast<const uint2*>(hin);
#pragma unroll
            for (int c = 0; c < 8; c++) {
                float4 v = h4_to_f4(__ldg(&h2[node * 16 + c0 + c]));
                r[4 * c + 0] = v.x;
                r[4 * c + 1] = v.y;
                r[4 * c + 2] = v.z;
                r[4 * c + 3] = v.w;
            }
        } else {
#pragma unroll
            for (int c = 0; c < 8; c++) {
                r[4 * c + 0] = 0.0f;
                r[4 * c + 1] = 0.0f;
                r[4 * c + 2] = 0.0f;
                r[4 * c + 3] = 0.0f;
            }
        }
    }
    __syncthreads();                      // W + rows ready

    int nl = tid & 127;
    int halfOfs = (tid >> 7) << 5;        // 0 or 32
    bool active = (base + nl) < N;
    float* myrow = rows + nl * 65;
    unsigned long long acc[16];

    // stage 1
    if (active) mlp_half_acc(myrow, Ws, halfOfs, b1, acc);
    __syncthreads();                      // all reads of input rows done
    if (active) mlp_half_store(myrow, halfOfs, acc);
    __syncthreads();                      // stage-1 outputs visible

    // stage 2
    if (active) mlp_half_acc(myrow, Ws + 4096, halfOfs, b2, acc);
    __syncthreads();
    if (active) mlp_half_store(myrow, halfOfs, acc);
    __syncthreads();                      // rows final for phase 3

    if (WRITE_H) {
        __half2* ho = reinterpret_cast<__half2*>(hout);
        for (int i = tid; i < 128 * 32; i += 256) {
            int r = i >> 5, c = (i & 31) << 1;
            if (base + r < N) {
                ho[(base + r) * 32 + (i & 31)] = __float22half2_rn(
                    make_float2(rows[r * 65 + c], rows[r * 65 + c + 1]));
            }
        }
    }

    // 4-duty phase 3 (padded rows are zero):
    //   duty 0/1: segmented pool sums + total, rows [0,64) / [64,128)
    //   duty 2/3: sum of squares,             rows [0,64) / [64,128)
    {
        int j    = tid & 63;
        int duty = tid >> 6;
        int r0 = (duty & 1) << 6, r1 = r0 + 64;
        if (duty < 2) {
            int cur = bats[r0];
            float acc2 = 0.0f;
            float tot = 0.0f;
            for (int r = r0; r < r1; r++) {
                int g = bats[r];
                float v = rows[r * 65 + j];
                if (g != cur) {
                    atomicAdd(&pool[cur * DIM + j], acc2);
                    acc2 = 0.0f;
                    cur = g;
                }
                acc2 += v;
                tot += v;
            }
            atomicAdd(&pool[cur * DIM + j], acc2);
            atomicAdd(&totsum[j], tot);
        } else {
            float s = 0.0f;
            for (int r = r0; r < r1; r++) {
                float v = rows[r * 65 + j];
                s += v * v;
            }
            atomicAdd(&stats[j], s);
        }
    }
}

// ---------------- output write (BN folded, scale/shift inline) -------------
__global__ void outwrite_kernel(const float* __restrict__ ps,
                                const float* __restrict__ gamma,
                                const float* __restrict__ beta,
                                float* __restrict__ out, int col_off,
                                float invN, int G) {
    int idx = blockIdx.x * blockDim.x + threadIdx.x;
    if (idx >= G * DIM) return;
    int g = idx >> 6, j = idx & 63;
    float mean = __ldg(ps + MAX_G * DIM + DIM + j) * invN;
    float var  = __ldg(ps + MAX_G * DIM + j) * invN - mean * mean;
    float sc   = __ldg(gamma + j) * rsqrtf(var + BN_EPS);
    float sh   = __ldg(beta + j) - mean * sc;
    out[g * 128 + col_off + j] = sc * ps[idx] + (float)__ldg(&CNTP[g]) * sh;
}

// ---------------------------------------------------------------------------
extern "C" void kernel_launch(void* const* d_in, const int* in_sizes, int n_in,
                              void* d_out, int out_size) {
    const float* x       = (const float*)d_in[0];
    const float* W1_0    = (const float*)d_in[1];
    const float* b1_0    = (const float*)d_in[2];
    const float* W2_0    = (const float*)d_in[3];
    const float* b2_0    = (const float*)d_in[4];
    const float* gamma_0 = (const float*)d_in[5];
    const float* beta_0  = (const float*)d_in[6];
    const float* W1_1    = (const float*)d_in[7];
    const float* b1_1    = (const float*)d_in[8];
    const float* W2_1    = (const float*)d_in[9];
    const float* b2_1    = (const float*)d_in[10];
    const float* gamma_1 = (const float*)d_in[11];
    const float* beta_1  = (const float*)d_in[12];
    const int*   ei      = (const int*)d_in[13];
    const int*   batch   = (const int*)d_in[14];

    int N = in_sizes[0] / DIM;
    int E = in_sizes[13] / 2;
    int G = out_size / 128;
    float* out = (float*)d_out;

    void *zero_p, *xh_p, *h0_p, *hin_p;
    cudaGetSymbolAddress(&zero_p, g_zeroed);
    cudaGetSymbolAddress(&xh_p, g_xh);
    cudaGetSymbolAddress(&h0_p, g_h0h);
    cudaGetSymbolAddress(&hin_p, g_hin);

    float* ps0 = (float*)zero_p;
    float* ps1 = ps0 + PS_FLOATS;

    cudaFuncSetAttribute(mlp_kernel<true>,
                         cudaFuncAttributeMaxDynamicSharedMemorySize,
                         MLP_SMEM_BYTES);
    cudaFuncSetAttribute(mlp_kernel<false>,
                         cudaFuncAttributeMaxDynamicSharedMemorySize,
                         MLP_SMEM_BYTES);

    int CV = N * DIM / 4;   // float4 conversion threads
    int work = (E > N) ? E : N;
    int fill_blocks = (work + 255) / 256;
    int cvt_blocks  = (CV + 255) / 256;
    int agg_blocks  = (N + 7) / 8;
    int ow_tail     = (G * DIM + 127) / 128;
    int mlp_blocks  = (N + 127) / 128;
    int ow_blocks   = (G * DIM + 255) / 256;
    float invN = 1.0f / (float)N;

    // ---- one memset for all zeroed scratch ----
    cudaMemsetAsync(zero_p, 0, sizeof(g_zeroed));
    fill_cnt_kernel<<<fill_blocks, 256>>>(ei, batch, E, N);
    cvt_kernel<<<cvt_blocks, 256>>>(x, CV);

    // ---------------- layer 0 ----------------
    aggregate_kernel<false><<<agg_blocks, 128>>>(
        (const __half*)xh_p, (__half*)hin_p, nullptr, nullptr, nullptr,
        nullptr, invN, N, G, agg_blocks);
    mlp_kernel<true><<<mlp_blocks, 256, MLP_SMEM_BYTES>>>(
        (const __half*)hin_p, W1_0, b1_0, W2_0, b2_0, batch,
        (__half*)h0_p, ps0, N);

    // ---------------- layer 1 (agg folds BN0 inline; tail = outwrite0) -----
    aggregate_kernel<true><<<agg_blocks + ow_tail, 128>>>(
        (const __half*)h0_p, (__half*)hin_p, ps0, gamma_0, beta_0, out,
        invN, N, G, agg_blocks);
    mlp_kernel<false><<<mlp_blocks, 256, MLP_SMEM_BYTES>>>(
        (const __half*)hin_p, W1_1, b1_1, W2_1, b2_1, batch,
        nullptr, ps1, N);
    outwrite_kernel<<<ow_blocks, 256>>>(ps1, gamma_1, beta_1, out, 64, invN, G);
}

// round 16
// speedup vs baseline: 1.9306x; 1.8394x over previous
#include <cuda_runtime.h>
#include <cuda_fp16.h>
#include <cstdint>

// ---------------------------------------------------------------------------
// GIN encoder. Bucketed-CSR pipeline + algebraic BN fold, 8 launches:
//   memset -> fill -> cvt(x->fp16 + weight [n][k] fp16 prep) -> agg0
//   -> mlp0(HMMA) -> agg1(+ow0 tail) -> mlp1(HMMA) -> ow1
// MLP = warp-level mma.sync m16n8k16: each warp owns 32 rows, computes all
// 64 outputs -> both stages warp-synchronous (no inter-stage barriers).
//   out[g] = scale * poolsum_preBN[g] + cnt[g] * shift
//   hin1   = sc0*(h0[n] + sum h0[src]) + (1+deg)*sh0     (x0 never stored)
// ---------------------------------------------------------------------------

#define MAX_N 100000
#define MAX_G 1024
#define DIM 64
#define BN_EPS 1e-5f
#define SLOTS 64
#define RS 72              // smem row stride in halves (conflict-free)

#define PS_FLOATS (MAX_G * DIM + 2 * DIM)

__device__ __align__(16) unsigned int g_zeroed[2 * PS_FLOATS + MAX_N + MAX_G];
#define DEGP ((int*)g_zeroed + 2 * PS_FLOATS)
#define CNTP (DEGP + MAX_N)

__device__ __align__(16) __half g_xh [MAX_N * DIM];  // fp16 copy of x
__device__ __align__(16) __half g_h0h[MAX_N * DIM];  // layer-0 pre-BN h, fp16
__device__ __align__(16) __half g_hin[MAX_N * DIM];  // MLP inputs, fp16
__device__ __align__(16) int g_srcidx[MAX_N * SLOTS];
// 4 weight matrices fp16, layout [n][k] stride RS (B-operand ready)
__device__ __align__(16) __half g_wh[4 * 64 * RS];

// ---------------- helpers --------------------------------------------------
static __device__ __forceinline__ float tanha(float x) {
    float y;
    asm("tanh.approx.f32 %0, %1;" : "=f"(y) : "f"(x));
    return y;
}
static __device__ __forceinline__ float4 h4_to_f4(uint2 v) {
    __half2 a = *reinterpret_cast<__half2*>(&v.x);
    __half2 b = *reinterpret_cast<__half2*>(&v.y);
    float2 fa = __half22float2(a);
    float2 fb = __half22float2(b);
    return make_float4(fa.x, fa.y, fb.x, fb.y);
}
static __device__ __forceinline__ uint2 f4_to_h4(float4 f) {
    __half2 a = __float22half2_rn(make_float2(f.x, f.y));
    __half2 b = __float22half2_rn(make_float2(f.z, f.w));
    uint2 v;
    v.x = *reinterpret_cast<unsigned int*>(&a);
    v.y = *reinterpret_cast<unsigned int*>(&b);
    return v;
}
static __device__ __forceinline__ void mma16816(
    float* c, const uint32_t* a, const uint32_t* b) {
    asm volatile(
        "mma.sync.aligned.m16n8k16.row.col.f32.f16.f16.f32 "
        "{%0,%1,%2,%3}, {%4,%5,%6,%7}, {%8,%9}, {%0,%1,%2,%3};"
        : "+f"(c[0]), "+f"(c[1]), "+f"(c[2]), "+f"(c[3])
        : "r"(a[0]), "r"(a[1]), "r"(a[2]), "r"(a[3]), "r"(b[0]), "r"(b[1]));
}

// ---------------- bucket fill + graph counts -------------------------------
__global__ void fill_cnt_kernel(const int* __restrict__ ei,
                                const int* __restrict__ batch, int E, int N) {
    int t = blockIdx.x * blockDim.x + threadIdx.x;
    if (t < E) {
        int s = __ldg(ei + t);
        int d = __ldg(ei + E + t);
        int pos = atomicAdd(&DEGP[d], 1);
        if (pos < SLOTS) g_srcidx[d * SLOTS + pos] = s;
    }
    if (t < N) atomicAdd(&CNTP[__ldg(batch + t)], 1);
}

// ---------------- x -> fp16 + weight [n][k] fp16 prep ----------------------
__global__ void cvt_kernel(const float* __restrict__ x,
                           const float* __restrict__ W1_0,
                           const float* __restrict__ W2_0,
                           const float* __restrict__ W1_1,
                           const float* __restrict__ W2_1, int CV) {
    int t = blockIdx.x * blockDim.x + threadIdx.x;
    if (t < CV) {
        float4 v = __ldg(&reinterpret_cast<const float4*>(x)[t]);
        reinterpret_cast<uint2*>(g_xh)[t] = f4_to_h4(v);
    }
    if (t < 4 * 4096) {
        int m = t >> 12, e = t & 4095;
        int k = e >> 6, j = e & 63;   // W[k][j] -> B[n=j][k]
        const float* W = (m == 0) ? W1_0 : (m == 1) ? W2_0
                       : (m == 2) ? W1_1 : W2_1;
        g_wh[m * 64 * RS + j * RS + k] = __float2half(__ldg(W + k * 64 + j));
    }
}

// ---------------- aggregation (fp16 gather, fp32 accumulate) ---------------
template <bool AFFINE>
__global__ __launch_bounds__(128) void aggregate_kernel(
    const __half* __restrict__ xh, __half* __restrict__ hout,
    const float* __restrict__ psPrev,
    const float* __restrict__ gamma, const float* __restrict__ beta,
    float* __restrict__ out, float invN, int N, int G, int aggBlocks) {
    if (AFFINE && (int)blockIdx.x >= aggBlocks) {
        int idx = ((int)blockIdx.x - aggBlocks) * 128 + threadIdx.x;
        if (idx < G * DIM) {
            int g = idx >> 6, j = idx & 63;
            float mean = __ldg(psPrev + MAX_G * DIM + DIM + j) * invN;
            float var  = __ldg(psPrev + MAX_G * DIM + j) * invN - mean * mean;
            float sc   = __ldg(gamma + j) * rsqrtf(var + BN_EPS);
            float sh   = __ldg(beta + j) - mean * sc;
            out[g * 128 + j] =
                sc * psPrev[idx] + (float)__ldg(&CNTP[g]) * sh;
        }
        return;
    }
    int node = blockIdx.x * 8 + (threadIdx.x >> 4);
    int c = threadIdx.x & 15;
    if (node >= N) return;
    int deg = __ldg(&DEGP[node]);
    const uint2* x2 = reinterpret_cast<const uint2*>(xh);
    const int4* idx4 = reinterpret_cast<const int4*>(g_srcidx + node * SLOTS);
    float4 acc = h4_to_f4(__ldg(&x2[node * 16 + c]));
    int e = 0;
    for (; e + 4 <= deg; e += 4) {
        int4 s = __ldg(&idx4[e >> 2]);
        float4 v0 = h4_to_f4(__ldg(&x2[s.x * 16 + c]));
        float4 v1 = h4_to_f4(__ldg(&x2[s.y * 16 + c]));
        float4 v2 = h4_to_f4(__ldg(&x2[s.z * 16 + c]));
        float4 v3 = h4_to_f4(__ldg(&x2[s.w * 16 + c]));
        acc.x += (v0.x + v1.x) + (v2.x + v3.x);
        acc.y += (v0.y + v1.y) + (v2.y + v3.y);
        acc.z += (v0.z + v1.z) + (v2.z + v3.z);
        acc.w += (v0.w + v1.w) + (v2.w + v3.w);
    }
    for (; e < deg; e++) {
        int s = __ldg(g_srcidx + node * SLOTS + e);
        float4 v0 = h4_to_f4(__ldg(&x2[s * 16 + c]));
        acc.x += v0.x;
        acc.y += v0.y;
        acc.z += v0.z;
        acc.w += v0.w;
    }
    if (AFFINE) {
        const float4* ss4 = reinterpret_cast<const float4*>(psPrev + MAX_G * DIM);
        const float4* ts4 = reinterpret_cast<const float4*>(psPrev + MAX_G * DIM + DIM);
        float4 ssq = __ldg(&ss4[c]);
        float4 tot = __ldg(&ts4[c]);
        float4 gm = __ldg(&reinterpret_cast<const float4*>(gamma)[c]);
        float4 bt = __ldg(&reinterpret_cast<const float4*>(beta)[c]);
        float f = (float)(1 + deg);
        float mx = tot.x * invN, my = tot.y * invN,
              mz = tot.z * invN, mw = tot.w * invN;
        float scx = gm.x * rsqrtf(ssq.x * invN - mx * mx + BN_EPS);
        float scy = gm.y * rsqrtf(ssq.y * invN - my * my + BN_EPS);
        float scz = gm.z * rsqrtf(ssq.z * invN - mz * mz + BN_EPS);
        float scw = gm.w * rsqrtf(ssq.w * invN - mw * mw + BN_EPS);
        acc.x = acc.x * scx + f * (bt.x - mx * scx);
        acc.y = acc.y * scy + f * (bt.y - my * scy);
        acc.z = acc.z * scz + f * (bt.z - mz * scz);
        acc.w = acc.w * scw + f * (bt.w - mw * scw);
    }
    reinterpret_cast<uint2*>(hout)[node * 16 + c] = f4_to_h4(acc);
}

// ---------------- MLP via mma.sync m16n8k16 --------------------------------
// 128 nodes / 128 threads (4 warps). Warp w owns rows [32w, 32w+32): two
// 16-row m-tiles x eight 8-col n-tiles x four k-steps per stage.
// A and stage outputs live in rows_h (fp16, stride RS); B = weights [n][k].
template <bool WRITE_H>
__global__ __launch_bounds__(128) void mlp_kernel(
    const __half* __restrict__ hin,
    const __half* __restrict__ W1h, const float* __restrict__ b1,
    const __half* __restrict__ W2h, const float* __restrict__ b2,
    const int* __restrict__ batch, __half* __restrict__ hout,
    float* __restrict__ ps, int N) {
    __shared__ __half rows_h[128 * RS];
    __shared__ __half W1s[64 * RS];
    __shared__ __half W2s[64 * RS];
    __shared__ float bias1[64], bias2[64];
    __shared__ int bats[128];

    float* pool   = ps;
    float* stats  = ps + MAX_G * DIM;
    float* totsum = ps + MAX_G * DIM + DIM;

    int tid  = threadIdx.x;
    int wid  = tid >> 5;
    int lane = tid & 31;
    int base = blockIdx.x * 128;
    int node = base + tid;
    bool active = node < N;

    // weights to smem (64*RS halves = 576 uint4 each; both matrices)
    {
        const uint4* s1 = reinterpret_cast<const uint4*>(W1h);
        const uint4* s2 = reinterpret_cast<const uint4*>(W2h);
        uint4* d1 = reinterpret_cast<uint4*>(W1s);
        uint4* d2 = reinterpret_cast<uint4*>(W2s);
        for (int i = tid; i < 64 * RS / 8; i += 128) {
            d1[i] = __ldg(s1 + i);
            d2[i] = __ldg(s2 + i);
        }
    }
    if (tid < 64) {
        bias1[tid] = __ldg(b1 + tid);
        bias2[tid] = __ldg(b2 + tid);
    }
    bats[tid] = __ldg(batch + (active ? node : N - 1));

    // stage my activation row into rows_h
    {
        uint2* dst = reinterpret_cast<uint2*>(rows_h + tid * RS);
        if (active) {
            const uint2* h2 = reinterpret_cast<const uint2*>(hin);
#pragma unroll
            for (int c2 = 0; c2 < 16; c2++) dst[c2] = __ldg(&h2[node * 16 + c2]);
        } else {
#pragma unroll
            for (int c2 = 0; c2 < 16; c2++) dst[c2] = make_uint2(0u, 0u);
        }
    }
    __syncthreads();

    int gid  = lane >> 2;      // 0..7
    int tq   = lane & 3;       // 0..3
    int mrow = wid * 32 + gid; // mtile-0 thread row
    const int RW = RS / 2;     // row stride in words (36)
    uint32_t* Rw = reinterpret_cast<uint32_t*>(rows_h);

    float acc[2][8][4];

#pragma unroll 1
    for (int stage = 0; stage < 2; stage++) {
        const uint32_t* Bw = reinterpret_cast<const uint32_t*>(
            stage == 0 ? W1s : W2s);
        const float* bs = stage == 0 ? bias1 : bias2;

        // init accumulators with bias (C frag cols = tq*2, tq*2+1)
#pragma unroll
        for (int mt = 0; mt < 2; mt++)
#pragma unroll
            for (int nt = 0; nt < 8; nt++) {
                float b0v = bs[nt * 8 + tq * 2];
                float b1v = bs[nt * 8 + tq * 2 + 1];
                acc[mt][nt][0] = b0v;
                acc[mt][nt][1] = b1v;
                acc[mt][nt][2] = b0v;
                acc[mt][nt][3] = b1v;
            }
        // k-steps
#pragma unroll
        for (int ks = 0; ks < 4; ks++) {
            int kw = ks * 8 + tq;              // word offset within row
            uint32_t a[2][4];
#pragma unroll
            for (int mt = 0; mt < 2; mt++) {
                int m0 = mrow + mt * 16;
                a[mt][0] = Rw[m0 * RW + kw];
                a[mt][1] = Rw[(m0 + 8) * RW + kw];
                a[mt][2] = Rw[m0 * RW + kw + 4];
                a[mt][3] = Rw[(m0 + 8) * RW + kw + 4];
            }
            uint32_t b[8][2];
#pragma unroll
            for (int nt = 0; nt < 8; nt++) {
                int n = nt * 8 + gid;
                b[nt][0] = Bw[n * RW + kw];
                b[nt][1] = Bw[n * RW + kw + 4];
            }
#pragma unroll
            for (int mt = 0; mt < 2; mt++)
#pragma unroll
                for (int nt = 0; nt < 8; nt++)
                    mma16816(acc[mt][nt], a[mt], b[nt]);
        }
        // epilogue: tanh -> fp16 back into rows_h (warp-local rows only)
#pragma unroll
        for (int mt = 0; mt < 2; mt++)
#pragma unroll
            for (int nt = 0; nt < 8; nt++) {
                int m = mrow + mt * 16;
                int nw = (nt * 8 + tq * 2) >> 1;  // word col
                __half2 h0 = __float22half2_rn(make_float2(
                    tanha(acc[mt][nt][0]), tanha(acc[mt][nt][1])));
                __half2 h1 = __float22half2_rn(make_float2(
                    tanha(acc[mt][nt][2]), tanha(acc[mt][nt][3])));
                Rw[m * RW + nw] = *reinterpret_cast<uint32_t*>(&h0);
                Rw[(m + 8) * RW + nw] = *reinterpret_cast<uint32_t*>(&h1);
            }
        __syncwarp();
    }
    __syncthreads();

    // zero padded rows (MMA gave them tanh(bias) != 0)
    if (!active) {
        uint2* dst = reinterpret_cast<uint2*>(rows_h + tid * RS);
#pragma unroll
        for (int c2 = 0; c2 < 16; c2++) dst[c2] = make_uint2(0u, 0u);
    }
    __syncthreads();

    if (WRITE_H) {
        __half2* ho = reinterpret_cast<__half2*>(hout);
        for (int i = tid; i < 128 * 32; i += 128) {
            int r = i >> 5, w = i & 31;
            if (base + r < N) {
                ho[(base + r) * 32 + w] =
                    *reinterpret_cast<__half2*>(&Rw[r * RW + w]);
            }
        }
    }

    // phase 3: threads 0..63 pool sums + total; 64..127 sum of squares
    if (tid < 64) {
        int j = tid;
        int cur = bats[0];
        float acc2 = 0.0f;
        float tot = 0.0f;
        for (int r = 0; r < 128; r++) {
            int g = bats[r];
            float v = __half2float(rows_h[r * RS + j]);
            if (g != cur) {
                atomicAdd(&pool[cur * DIM + j], acc2);
                acc2 = 0.0f;
                cur = g;
            }
            acc2 += v;
            tot += v;
        }
        atomicAdd(&pool[cur * DIM + j], acc2);
        atomicAdd(&totsum[j], tot);
    } else {
        int j = tid - 64;
        float s = 0.0f;
        for (int r = 0; r < 128; r++) {
            float v = __half2float(rows_h[r * RS + j]);
            s += v * v;
        }
        atomicAdd(&stats[j], s);
    }
}

// ---------------- output write (BN folded, scale/shift inline) -------------
__global__ void outwrite_kernel(const float* __restrict__ ps,
                                const float* __restrict__ gamma,
                                const float* __restrict__ beta,
                                float* __restrict__ out, int col_off,
                                float invN, int G) {
    int idx = blockIdx.x * blockDim.x + threadIdx.x;
    if (idx >= G * DIM) return;
    int g = idx >> 6, j = idx & 63;
    float mean = __ldg(ps + MAX_G * DIM + DIM + j) * invN;
    float var  = __ldg(ps + MAX_G * DIM + j) * invN - mean * mean;
    float sc   = __ldg(gamma + j) * rsqrtf(var + BN_EPS);
    float sh   = __ldg(beta + j) - mean * sc;
    out[g * 128 + col_off + j] = sc * ps[idx] + (float)__ldg(&CNTP[g]) * sh;
}

// ---------------------------------------------------------------------------
extern "C" void kernel_launch(void* const* d_in, const int* in_sizes, int n_in,
                              void* d_out, int out_size) {
    const float* x       = (const float*)d_in[0];
    const float* W1_0    = (const float*)d_in[1];
    const float* b1_0    = (const float*)d_in[2];
    const float* W2_0    = (const float*)d_in[3];
    const float* b2_0    = (const float*)d_in[4];
    const float* gamma_0 = (const float*)d_in[5];
    const float* beta_0  = (const float*)d_in[6];
    const float* W1_1    = (const float*)d_in[7];
    const float* b1_1    = (const float*)d_in[8];
    const float* W2_1    = (const float*)d_in[9];
    const float* b2_1    = (const float*)d_in[10];
    const float* gamma_1 = (const float*)d_in[11];
    const float* beta_1  = (const float*)d_in[12];
    const int*   ei      = (const int*)d_in[13];
    const int*   batch   = (const int*)d_in[14];

    int N = in_sizes[0] / DIM;
    int E = in_sizes[13] / 2;
    int G = out_size / 128;
    float* out = (float*)d_out;

    void *zero_p, *xh_p, *h0_p, *hin_p, *wh_p;
    cudaGetSymbolAddress(&zero_p, g_zeroed);
    cudaGetSymbolAddress(&xh_p, g_xh);
    cudaGetSymbolAddress(&h0_p, g_h0h);
    cudaGetSymbolAddress(&hin_p, g_hin);
    cudaGetSymbolAddress(&wh_p, g_wh);

    float* ps0 = (float*)zero_p;
    float* ps1 = ps0 + PS_FLOATS;
    const __half* wh = (const __half*)wh_p;

    int CV = N * DIM / 4;
    int work = (E > N) ? E : N;
    int fill_blocks = (work + 255) / 256;
    int cvt_work = (CV > 4 * 4096) ? CV : 4 * 4096;
    int cvt_blocks  = (cvt_work + 255) / 256;
    int agg_blocks  = (N + 7) / 8;
    int ow_tail     = (G * DIM + 127) / 128;
    int mlp_blocks  = (N + 127) / 128;
    int ow_blocks   = (G * DIM + 255) / 256;
    float invN = 1.0f / (float)N;

    cudaMemsetAsync(zero_p, 0, sizeof(g_zeroed));
    fill_cnt_kernel<<<fill_blocks, 256>>>(ei, batch, E, N);
    cvt_kernel<<<cvt_blocks, 256>>>(x, W1_0, W2_0, W1_1, W2_1, CV);

    // ---------------- layer 0 ----------------
    aggregate_kernel<false><<<agg_blocks, 128>>>(
        (const __half*)xh_p, (__half*)hin_p, nullptr, nullptr, nullptr,
        nullptr, invN, N, G, agg_blocks);
    mlp_kernel<true><<<mlp_blocks, 128>>>(
        (const __half*)hin_p, wh, b1_0, wh + 64 * RS, b2_0, batch,
        (__half*)h0_p, ps0, N);

    // ---------------- layer 1 (agg folds BN0 inline; tail = outwrite0) -----
    aggregate_kernel<true><<<agg_blocks + ow_tail, 128>>>(
        (const __half*)h0_p, (__half*)hin_p, ps0, gamma_0, beta_0, out,
        invN, N, G, agg_blocks);
    mlp_kernel<false><<<mlp_blocks, 128>>>(
        (const __half*)hin_p, wh + 2 * 64 * RS, b1_1, wh + 3 * 64 * RS, b2_1,
        batch, nullptr, ps1, N);
    outwrite_kernel<<<ow_blocks, 256>>>(ps1, gamma_1, beta_1, out, 64, invN, G);
}